// round 3
// baseline (speedup 1.0000x reference)
#include <cuda_runtime.h>
#include <cstdint>

#define B_ROWS     524288
#define D_DIM      64
#define TILE       128
#define THREADS    128
#define GRID       888            // 148 SMs * 6 blocks/SM
#define NTILES     (B_ROWS / TILE)   // 4096
#define ROW_STRIDE 68             // floats; pad 64->68 for conflict-free LDS.128

__device__ double g_acc;

__global__ void mcl_init() { g_acc = 0.0; }

__device__ __forceinline__ void cp_async16(uint32_t saddr, const void* gptr) {
    asm volatile("cp.async.cg.shared.global [%0], [%1], 16;\n"
                 :: "r"(saddr), "l"(gptr) : "memory");
}

__global__ void __launch_bounds__(THREADS) mcl_main(
    const float* __restrict__ x,
    const int*   __restrict__ labels,     // int32 (JAX x64-disabled downcasts int64)
    const float* __restrict__ lin_w,
    const float* __restrict__ lin_b,
    const float* __restrict__ linear_p,
    const float* __restrict__ bias_p,
    const float* __restrict__ centers)
{
    __shared__ __align__(16) float sx[TILE * ROW_STRIDE];
    __shared__ __align__(16) float sw[D_DIM];
    __shared__ float warp_acc[THREADS / 32];

    const int tid = threadIdx.x;
    if (tid < D_DIM / 4)
        ((float4*)sw)[tid] = ((const float4*)lin_w)[tid];
    const float lb = __ldg(lin_b);

    float acc = 0.f;

    for (int tile = blockIdx.x; tile < NTILES; tile += GRID) {
        const float4* gx = (const float4*)(x + (size_t)tile * TILE * D_DIM);

        // guard smem reuse from previous iteration's compute; also makes sw visible
        __syncthreads();

        // stage 128 rows * 256B = 32KB via cp.async (coalesced gmem, padded smem)
        #pragma unroll
        for (int k = 0; k < 16; k++) {
            int f   = k * THREADS + tid;   // float4 index within tile
            int row = f >> 4;
            int c4  = f & 15;
            uint32_t saddr = (uint32_t)__cvta_generic_to_shared(
                &sx[row * ROW_STRIDE + c4 * 4]);
            cp_async16(saddr, gx + f);
        }
        asm volatile("cp.async.commit_group;\n" ::: "memory");

        // prefetch this thread's label while the tile is in flight
        int lab = __ldg(&labels[(size_t)tile * TILE + tid]);
        lab = min(max(lab, 0), 999);   // crash-proof the gather

        asm volatile("cp.async.wait_group 0;\n" ::: "memory");
        __syncthreads();

        // each thread reduces its own row from shared (conflict-free LDS.128)
        const float4* xr = (const float4*)(&sx[tid * ROW_STRIDE]);
        float m = 0.f, s = 0.f, q = 0.f;
        #pragma unroll
        for (int j = 0; j < 16; j++) {
            float4 v = xr[j];
            float4 w = ((const float4*)sw)[j];
            m = fmaf(v.x, w.x, m); m = fmaf(v.y, w.y, m);
            m = fmaf(v.z, w.z, m); m = fmaf(v.w, w.w, m);
            s += (v.x + v.y) + (v.z + v.w);
            q = fmaf(v.x, v.x, q); q = fmaf(v.y, v.y, q);
            q = fmaf(v.z, v.z, q); q = fmaf(v.w, v.w, q);
        }
        m += lb;

        const int l3 = lab * 3;
        const float A0 = __ldg(linear_p + l3 + 0);
        const float A1 = __ldg(linear_p + l3 + 1);
        const float A2 = __ldg(linear_p + l3 + 2);
        const float B0 = __ldg(bias_p   + l3 + 0);
        const float B1 = __ldg(bias_p   + l3 + 1);
        const float B2 = __ldg(bias_p   + l3 + 2);
        const float C0 = __ldg(centers  + l3 + 0);
        const float C1 = __ldg(centers  + l3 + 1);
        const float C2 = __ldg(centers  + l3 + 2);

        const float l0 = fmaf(m, A0, B0);
        const float l1 = fmaf(m, A1, B1);
        const float l2 = fmaf(m, A2, B2);
        const float mx = fmaxf(l0, fmaxf(l1, l2));
        const float e0 = __expf(l0 - mx);
        const float e1 = __expf(l1 - mx);
        const float e2 = __expf(l2 - mx);
        const float inv = 1.f / (e0 + e1 + e2);

        // sum_k gamma_k * sqdist_k = q + sum_k gamma_k * C_k*(64*C_k - 2*s)
        const float t0 = C0 * fmaf(64.f, C0, -2.f * s);
        const float t1 = C1 * fmaf(64.f, C1, -2.f * s);
        const float t2 = C2 * fmaf(64.f, C2, -2.f * s);
        acc += q + inv * (e0 * t0 + e1 * t1 + e2 * t2);
    }

    // block reduction -> one double atomic per block
    #pragma unroll
    for (int o = 16; o > 0; o >>= 1)
        acc += __shfl_xor_sync(0xffffffffu, acc, o);
    if ((tid & 31) == 0)
        warp_acc[tid >> 5] = acc;
    __syncthreads();
    if (tid == 0) {
        float t = 0.f;
        #pragma unroll
        for (int i = 0; i < THREADS / 32; i++) t += warp_acc[i];
        atomicAdd(&g_acc, (double)t);
    }
}

__global__ void mcl_fin(float* __restrict__ out) {
    out[0] = (float)(g_acc / (double)B_ROWS);
}

extern "C" void kernel_launch(void* const* d_in, const int* in_sizes, int n_in,
                              void* d_out, int out_size)
{
    const float* x        = (const float*)d_in[0];
    const int*   labels   = (const int*)d_in[1];
    const float* lin_w    = (const float*)d_in[2];
    const float* lin_b    = (const float*)d_in[3];
    const float* linear_p = (const float*)d_in[4];
    const float* bias_p   = (const float*)d_in[5];
    const float* centers  = (const float*)d_in[6];

    mcl_init<<<1, 1>>>();
    mcl_main<<<GRID, THREADS>>>(x, labels, lin_w, lin_b, linear_p, bias_p, centers);
    mcl_fin<<<1, 1>>>((float*)d_out);
}